// round 14
// baseline (speedup 1.0000x reference)
#include <cuda_runtime.h>
#include <cuda_fp16.h>
#include <cstdint>

#define Bc 128
#define Cc 64
#define Hc 32
#define Wc 32
#define NEDGE 6
#define TOTSZ (Bc*Cc*Hc*Wc)
#define WSZ   (NEDGE*Cc*Cc*9)

typedef unsigned int u32;

// ---------------- device scratch ----------------
__device__ __align__(16) __half d_x0[TOTSZ];
__device__ __align__(16) __half d_x1[TOTSZ];
__device__ __align__(16) __half d_x2[TOTSZ];
__device__ float d_acc2[TOTSZ];     // NCHW fp32
__device__ float d_acc3[TOTSZ];     // NCHW fp32
__device__ __align__(16) __half d_wm[NEDGE*9*Cc*64];   // [l][s][oc][64] fp16
__device__ float d_ain[Cc], d_aout[Cc];

// ---------------- PTX helpers (baseline sm_80+ PTX only) ----------------
__device__ __forceinline__ u32 smem_u32(const void* p){
    u32 a; asm("{ .reg .u64 t; cvta.to.shared.u64 t, %1; cvt.u32.u64 %0, t; }":"=r"(a):"l"(p)); return a;
}
#define CP16(dst,src) asm volatile("cp.async.ca.shared.global [%0], [%1], 16;"::"r"(dst),"l"(src):"memory")
#define CPCOMMIT()    asm volatile("cp.async.commit_group;":::"memory")
#define CPWAIT1()     asm volatile("cp.async.wait_group 1;":::"memory")
#define CPWAIT0()     asm volatile("cp.async.wait_group 0;":::"memory")

#define LDSM4(r0,r1,r2,r3,addr) \
    asm volatile("ldmatrix.sync.aligned.m8n8.x4.shared.b16 {%0,%1,%2,%3}, [%4];" \
        : "=r"(r0),"=r"(r1),"=r"(r2),"=r"(r3) : "r"(addr))

#define MMAH(c,a0,a1,a2,a3,b0,b1) \
    asm volatile("mma.sync.aligned.m16n8k16.row.col.f32.f16.f16.f32 " \
        "{%0,%1,%2,%3},{%4,%5,%6,%7},{%8,%9},{%0,%1,%2,%3};" \
        : "+f"((c)[0]),"+f"((c)[1]),"+f"((c)[2]),"+f"((c)[3]) \
        : "r"(a0),"r"(a1),"r"(a2),"r"(a3),"r"(b0),"r"(b1))

// ---------------- prep kernels ----------------
__global__ void scales_kernel(const float* __restrict__ a1, const float* __restrict__ a2){
    int c = threadIdx.x;
    if (c < Cc){
        float s1=0.f, s2=0.f;
        #pragma unroll
        for (int i=0;i<8;i++) if (c < 8*(i+1)) { s1+=a1[i]; s2+=a2[i]; }
        d_ain[c]=s1; d_aout[c]=s2;
    }
}

__global__ void wprep_kernel(const float* __restrict__ W){
    int idx = blockIdx.x*256 + threadIdx.x;
    if (idx >= NEDGE*9*Cc*Cc) return;
    int ci = idx & 63, t = idx >> 6;
    int oc = t & 63; t >>= 6;
    int s = t % 9, l = t / 9;
    float w = W[(((l*Cc + oc)*Cc + ci)*9) + s];
    d_wm[(size_t)((l*9 + s)*Cc + oc) * 64 + ci] = __float2half_rn(w);
}

__global__ void inprep_kernel(const float* __restrict__ x){
    __shared__ float tile[Cc][Wc+1];
    int b = blockIdx.y, h = blockIdx.x, t = threadIdx.x;
    int w = t & 31, cb = t >> 5;
    #pragma unroll
    for (int i=0;i<8;i++){
        int c = cb*8 + i;
        tile[c][w] = x[(((size_t)b*Cc + c)*Hc + h)*Wc + w];
    }
    __syncthreads();
    int w2 = t >> 3, cg = (t & 7) * 8;
    u32 hi[4];
    #pragma unroll
    for (int i=0;i<4;i++){
        int c = cg + i*2;
        float v0 = d_ain[c]   * fmaxf(tile[c][w2],   0.f);
        float v1 = d_ain[c+1] * fmaxf(tile[c+1][w2], 0.f);
        hi[i]=(u32)__half_as_ushort(__float2half_rn(v0))
             |((u32)__half_as_ushort(__float2half_rn(v1))<<16);
    }
    size_t pos = ((size_t)b*Hc + h)*Wc + w2;
    *(uint4*)(d_x0 + pos*64 + cg) = make_uint4(hi[0],hi[1],hi[2],hi[3]);
}

// ---------------- conv pass (parametric, MT=4, full 64-oc CTAs) ----------------
struct PassSpec {
    int l[3];
    int mode[3];            // 0: fp32 NCHW acc; 1: relu -> next d_x fp16; 2: final NCHW out
    const float* addin[3];  // NCHW fp32 or null
    void* outA[3];
    const __half* in;
};

// Et edges, BAND rows/CTA, NT threads, OCC CTAs/SM.
// warps = (BAND/2 row-pairs) x MG m-groups; MT = 4*Et/MG = 4 m-tiles per warp (64 oc spread).
template<int Et, int BAND, int NT, int OCC>
__global__ __launch_bounds__(NT, OCC)
void conv_mma_kernel(PassSpec ps){
    constexpr int WARPS = NT/32;
    constexpr int RP    = BAND/2;
    constexpr int MG    = WARPS/RP;
    constexpr int MT    = (Et*4)/MG;
    constexpr int INR   = BAND + 2;
    constexpr int SM_IN = INR*34*144;
    constexpr int WBUF  = Et*64*144;
    static_assert(MT == 4 && MG*MT == Et*4 && RP*MG == WARPS, "tiling");

    extern __shared__ __align__(16) char smem[];
    const u32 sb  = smem_u32(smem);
    const int tid = threadIdx.x;
    const int lane = tid & 31, wrp = tid >> 5;
    const int wn2 = wrp % RP, wm = wrp / RP;
    const int band = blockIdx.x, b = blockIdx.y;
    const int h0 = band * BAND;
    const u32 sbW = sb + SM_IN;

    // ---- stage input tile: INR*34 pos rows x 128B (+16B pad) ----
    for (int idx = tid; idx < INR*34*8; idx += NT){
        int p = idx >> 3, ch = idx & 7;
        int trow = p / 34, tcol = p - trow*34;
        int ih = h0 - 1 + trow, iw = tcol - 1;
        u32 dst = sb + p*144 + ch*16;
        if ((unsigned)ih < 32u && (unsigned)iw < 32u){
            const char* src = (const char*)(ps.in + ((size_t)((b*Hc + ih)*Wc + iw) << 6)) + ch*16;
            CP16(dst, src);
        } else {
            asm volatile("st.shared.v4.b32 [%0], {%1,%1,%1,%1};"::"r"(dst),"r"(0):"memory");
        }
    }
    // ---- stage weights (all 64 oc) tap 0 into buf 0 ----
    for (int idx = tid; idx < Et*512; idx += NT){
        int r = idx >> 3, ch = idx & 7;
        int e = r >> 6, rl = r & 63;
        u32 dst = sbW + r*144 + ch*16;
        const char* src = (const char*)d_wm + (((size_t)(ps.l[e]*9 + 0)*64 + rl) << 7) + ch*16;
        CP16(dst, src);
    }
    CPCOMMIT();

    // ldmatrix lane patterns
    const int g = lane >> 3, lm = lane & 7;
    const u32 patB = (u32)(((g&2)?8:0) + lm)*144 + ((g&1)?16:0);
    const u32 patA = (u32)(((g&1)?8:0) + lm)*144 + ((g&2)?16:0);

    float acc[4][8][4];
    #pragma unroll
    for (int j = 0; j < 4; j++)
        #pragma unroll
        for (int nt = 0; nt < 8; nt++)
            #pragma unroll
            for (int q = 0; q < 4; q++) acc[j][nt][q] = 0.f;

    #pragma unroll 1
    for (int tap = 0; tap < 9; tap++){
        if (tap + 1 < 9){
            int buf = (tap + 1) % 3;
            for (int idx = tid; idx < Et*512; idx += NT){
                int r = idx >> 3, ch = idx & 7;
                int e = r >> 6, rl = r & 63;
                u32 dst = sbW + buf*WBUF + r*144 + ch*16;
                const char* src = (const char*)d_wm + (((size_t)(ps.l[e]*9 + tap + 1)*64 + rl) << 7) + ch*16;
                CP16(dst, src);
            }
            CPCOMMIT();
            CPWAIT1();
        } else {
            CPWAIT0();
        }
        __syncthreads();   // single barrier per tap (triple-buffered weights)

        const int ky = tap / 3, kx = tap - ky*3;
        const u32 pB0 = sb + (u32)((wn2*2 + ky)*34 + kx)*144 + patB;
        const u32 pB1 = pB0 + 34*144;
        const u32 pA  = sbW + (tap % 3)*WBUF + (u32)(wm*4*16)*144 + patA;

        #pragma unroll
        for (int kk = 0; kk < 4; kk++){
            u32 b0,b1,b2,b3,b4,b5,b6,b7;
            u32 c0,c1,c2,c3,c4,c5,c6,c7;
            LDSM4(b0,b1,b2,b3, pB0 + 32*kk);
            LDSM4(b4,b5,b6,b7, pB0 + 32*kk + 16*144);
            LDSM4(c0,c1,c2,c3, pB1 + 32*kk);
            LDSM4(c4,c5,c6,c7, pB1 + 32*kk + 16*144);
            #pragma unroll
            for (int j = 0; j < 4; j++){
                u32 a0,a1,a2,a3;
                LDSM4(a0,a1,a2,a3, pA + j*(16*144) + 32*kk);
                MMAH(acc[j][0], a0,a1,a2,a3, b0,b1);
                MMAH(acc[j][1], a0,a1,a2,a3, b2,b3);
                MMAH(acc[j][2], a0,a1,a2,a3, b4,b5);
                MMAH(acc[j][3], a0,a1,a2,a3, b6,b7);
                MMAH(acc[j][4], a0,a1,a2,a3, c0,c1);
                MMAH(acc[j][5], a0,a1,a2,a3, c2,c3);
                MMAH(acc[j][6], a0,a1,a2,a3, c4,c5);
                MMAH(acc[j][7], a0,a1,a2,a3, c6,c7);
            }
        }
    }

    // ---------------- epilogue ----------------
    #pragma unroll
    for (int j = 0; j < 4; j++){
        int t = wm*4 + j;
        int e = t >> 2;
        int ocb = (t & 3)*16 + (lane >> 2);
        int mode = ps.mode[e];
        const float* add = ps.addin[e];
        #pragma unroll
        for (int nt = 0; nt < 8; nt++){
            int h = h0 + wn2*2 + (nt >> 2);
            int wcol = (nt & 3)*8 + 2*(lane & 3);
            #pragma unroll
            for (int half = 0; half < 2; half++){
                int oc = ocb + half*8;
                float v0 = acc[j][nt][half*2 + 0];
                float v1 = acc[j][nt][half*2 + 1];
                size_t base = (((size_t)b*Cc + oc)*Hc + h)*Wc + wcol;
                if (add){
                    float2 a2 = *(const float2*)(add + base);
                    v0 += a2.x; v1 += a2.y;
                }
                if (mode == 0){
                    *(float2*)((float*)ps.outA[e] + base) = make_float2(v0, v1);
                } else if (mode == 1){
                    float ai = d_ain[oc], ao = d_aout[oc];
                    v0 = ai * fmaxf(ao * v0, 0.f);
                    v1 = ai * fmaxf(ao * v1, 0.f);
                    __half* ox = (__half*)ps.outA[e];
                    size_t pos = ((size_t)b*Hc + h)*Wc + wcol;
                    ox[pos*64 + oc]     = __float2half_rn(v0);
                    ox[(pos+1)*64 + oc] = __float2half_rn(v1);
                } else {
                    float ao = d_aout[oc];
                    *(float2*)((float*)ps.outA[e] + base) = make_float2(ao*v0, ao*v1);
                }
            }
        }
    }
}

// ---------------- launch ----------------
extern "C" void kernel_launch(void* const* d_in, const int* in_sizes, int n_in,
                              void* d_out, int out_size){
    const float *x=nullptr, *a1=nullptr, *a2=nullptr, *W=nullptr;
    for (int i=0;i<n_in;i++){
        if (in_sizes[i]==TOTSZ) x=(const float*)d_in[i];
        else if (in_sizes[i]==WSZ) W=(const float*)d_in[i];
        else if (in_sizes[i]==8){ if(!a1) a1=(const float*)d_in[i]; else a2=(const float*)d_in[i]; }
    }
    float* out = (float*)d_out;

    __half *x0p,*x1p,*x2p;
    float *acc2,*acc3;
    cudaGetSymbolAddress((void**)&x0p,d_x0);
    cudaGetSymbolAddress((void**)&x1p,d_x1);
    cudaGetSymbolAddress((void**)&x2p,d_x2);
    cudaGetSymbolAddress((void**)&acc2,d_acc2);
    cudaGetSymbolAddress((void**)&acc3,d_acc3);

    // A: Et=3, band 4, NT=192 (2 RP x 3 MG), 2 CTAs/SM, smem 112320
    // B: Et=2, band 4, NT=128 (2 RP x 2 MG), 2 CTAs/SM, smem 84672
    // C: Et=1, band 8, NT=128 (4 RP x 1 MG), 2 CTAs/SM, smem 76608
    const int smemA = 6*34*144  + 3*3*64*144;   // 112320
    const int smemB = 6*34*144  + 3*2*64*144;   // 84672
    const int smemC = 10*34*144 + 3*1*64*144;   // 76608
    cudaFuncSetAttribute((conv_mma_kernel<3,4,192,2>), cudaFuncAttributeMaxDynamicSharedMemorySize, smemA);
    cudaFuncSetAttribute((conv_mma_kernel<2,4,128,2>), cudaFuncAttributeMaxDynamicSharedMemorySize, smemB);
    cudaFuncSetAttribute((conv_mma_kernel<1,8,128,2>), cudaFuncAttributeMaxDynamicSharedMemorySize, smemC);

    scales_kernel<<<1, 64>>>(a1, a2);
    wprep_kernel<<<(NEDGE*9*Cc*Cc + 255)/256, 256>>>(W);
    inprep_kernel<<<dim3(Hc, Bc), 256>>>(x);

    // Pass A: x0 -> { W0 -> x1 (mode1), W1 -> acc2 (mode0), W3 -> acc3 (mode0) }
    PassSpec pa{};
    pa.l[0]=0; pa.mode[0]=1; pa.addin[0]=nullptr; pa.outA[0]=x1p;
    pa.l[1]=1; pa.mode[1]=0; pa.addin[1]=nullptr; pa.outA[1]=acc2;
    pa.l[2]=3; pa.mode[2]=0; pa.addin[2]=nullptr; pa.outA[2]=acc3;
    pa.in = x0p;
    conv_mma_kernel<3,4,192,2><<<dim3(8, Bc, 1), 192, smemA>>>(pa);

    // Pass B: x1 -> { W2 + acc2 -> x2 (mode1), W4 + acc3 -> acc3 (mode0) }
    PassSpec pb{};
    pb.l[0]=2; pb.mode[0]=1; pb.addin[0]=acc2; pb.outA[0]=x2p;
    pb.l[1]=4; pb.mode[1]=0; pb.addin[1]=acc3; pb.outA[1]=acc3;
    pb.in = x1p;
    conv_mma_kernel<2,4,128,2><<<dim3(8, Bc, 1), 128, smemB>>>(pb);

    // Pass C: x2 -> { W5 + acc3 -> out (mode2) }
    PassSpec pc{};
    pc.l[0]=5; pc.mode[0]=2; pc.addin[0]=acc3; pc.outA[0]=out;
    pc.in = x2p;
    conv_mma_kernel<1,8,128,2><<<dim3(4, Bc, 1), 128, smemC>>>(pc);

    (void)out_size;
}

// round 15
// speedup vs baseline: 1.2395x; 1.2395x over previous
#include <cuda_runtime.h>
#include <cuda_fp16.h>
#include <cstdint>

#define Bc 128
#define Cc 64
#define Hc 32
#define Wc 32
#define NEDGE 6
#define TOTSZ (Bc*Cc*Hc*Wc)
#define WSZ   (NEDGE*Cc*Cc*9)

typedef unsigned int u32;

// ---------------- device scratch ----------------
__device__ __align__(16) __half d_x0[TOTSZ];
__device__ __align__(16) __half d_x1[TOTSZ];
__device__ __align__(16) __half d_x2[TOTSZ];
__device__ float d_acc2[TOTSZ];     // NCHW fp32
__device__ float d_acc3[TOTSZ];     // NCHW fp32
__device__ __align__(16) __half d_wm[NEDGE*9*Cc*64];   // [l][s][oc][64] fp16
__device__ float d_ain[Cc], d_aout[Cc];

// ---------------- PTX helpers (baseline sm_80+ PTX only) ----------------
__device__ __forceinline__ u32 smem_u32(const void* p){
    u32 a; asm("{ .reg .u64 t; cvta.to.shared.u64 t, %1; cvt.u32.u64 %0, t; }":"=r"(a):"l"(p)); return a;
}
#define CP16(dst,src) asm volatile("cp.async.ca.shared.global [%0], [%1], 16;"::"r"(dst),"l"(src):"memory")
#define CPCOMMIT()    asm volatile("cp.async.commit_group;":::"memory")
#define CPWAIT1()     asm volatile("cp.async.wait_group 1;":::"memory")
#define CPWAIT0()     asm volatile("cp.async.wait_group 0;":::"memory")

#define LDSM4(r0,r1,r2,r3,addr) \
    asm volatile("ldmatrix.sync.aligned.m8n8.x4.shared.b16 {%0,%1,%2,%3}, [%4];" \
        : "=r"(r0),"=r"(r1),"=r"(r2),"=r"(r3) : "r"(addr))

#define MMAH(c,a0,a1,a2,a3,b0,b1) \
    asm volatile("mma.sync.aligned.m16n8k16.row.col.f32.f16.f16.f32 " \
        "{%0,%1,%2,%3},{%4,%5,%6,%7},{%8,%9},{%0,%1,%2,%3};" \
        : "+f"((c)[0]),"+f"((c)[1]),"+f"((c)[2]),"+f"((c)[3]) \
        : "r"(a0),"r"(a1),"r"(a2),"r"(a3),"r"(b0),"r"(b1))

// ---------------- prep kernels ----------------
__global__ void scales_kernel(const float* __restrict__ a1, const float* __restrict__ a2){
    int c = threadIdx.x;
    if (c < Cc){
        float s1=0.f, s2=0.f;
        #pragma unroll
        for (int i=0;i<8;i++) if (c < 8*(i+1)) { s1+=a1[i]; s2+=a2[i]; }
        d_ain[c]=s1; d_aout[c]=s2;
    }
}

__global__ void wprep_kernel(const float* __restrict__ W){
    int idx = blockIdx.x*256 + threadIdx.x;
    if (idx >= NEDGE*9*Cc*Cc) return;
    int ci = idx & 63, t = idx >> 6;
    int oc = t & 63; t >>= 6;
    int s = t % 9, l = t / 9;
    float w = W[(((l*Cc + oc)*Cc + ci)*9) + s];
    d_wm[(size_t)((l*9 + s)*Cc + oc) * 64 + ci] = __float2half_rn(w);
}

__global__ void inprep_kernel(const float* __restrict__ x){
    __shared__ float tile[Cc][Wc+1];
    int b = blockIdx.y, h = blockIdx.x, t = threadIdx.x;
    int w = t & 31, cb = t >> 5;
    #pragma unroll
    for (int i=0;i<8;i++){
        int c = cb*8 + i;
        tile[c][w] = x[(((size_t)b*Cc + c)*Hc + h)*Wc + w];
    }
    __syncthreads();
    int w2 = t >> 3, cg = (t & 7) * 8;
    u32 hi[4];
    #pragma unroll
    for (int i=0;i<4;i++){
        int c = cg + i*2;
        float v0 = d_ain[c]   * fmaxf(tile[c][w2],   0.f);
        float v1 = d_ain[c+1] * fmaxf(tile[c+1][w2], 0.f);
        hi[i]=(u32)__half_as_ushort(__float2half_rn(v0))
             |((u32)__half_as_ushort(__float2half_rn(v1))<<16);
    }
    size_t pos = ((size_t)b*Hc + h)*Wc + w2;
    *(uint4*)(d_x0 + pos*64 + cg) = make_uint4(hi[0],hi[1],hi[2],hi[3]);
}

// ---------------- conv pass (parametric, och-split CTAs) ----------------
struct PassSpec {
    int l[3];
    int mode[3];            // 0: fp32 NCHW acc; 1: relu -> next d_x fp16; 2: final NCHW out
    const float* addin[3];  // NCHW fp32 or null
    void* outA[3];
    const __half* in;
};

// Et edges, BAND rows/CTA, NT threads, OCC CTAs/SM; CTA owns 32 oc (blockIdx.z half).
// warps = (BAND/2 row-pairs) x MG m-groups; MT = Et*2/MG m-tiles per warp, n=8.
template<int Et, int BAND, int NT, int OCC>
__global__ __launch_bounds__(NT, OCC)
void conv_mma_kernel(PassSpec ps){
    constexpr int WARPS = NT/32;
    constexpr int RP    = BAND/2;
    constexpr int MG    = WARPS/RP;
    constexpr int MT    = (Et*2)/MG;
    constexpr int INR   = BAND + 2;
    constexpr int SM_IN = INR*34*144;
    constexpr int WBUF  = Et*32*144;
    static_assert(MG*MT == Et*2 && RP*MG == WARPS, "tiling");

    extern __shared__ __align__(16) char smem[];
    const u32 sb  = smem_u32(smem);
    const int tid = threadIdx.x;
    const int lane = tid & 31, wrp = tid >> 5;
    const int wn2 = wrp % RP, wm = wrp / RP;
    const int band = blockIdx.x, b = blockIdx.y;
    const int och = blockIdx.z;
    const int h0 = band * BAND;
    const u32 sbW = sb + SM_IN;

    // ---- stage input tile: INR*34 pos rows x 128B (+16B pad) ----
    for (int idx = tid; idx < INR*34*8; idx += NT){
        int p = idx >> 3, ch = idx & 7;
        int trow = p / 34, tcol = p - trow*34;
        int ih = h0 - 1 + trow, iw = tcol - 1;
        u32 dst = sb + p*144 + ch*16;
        if ((unsigned)ih < 32u && (unsigned)iw < 32u){
            const char* src = (const char*)(ps.in + ((size_t)((b*Hc + ih)*Wc + iw) << 6)) + ch*16;
            CP16(dst, src);
        } else {
            asm volatile("st.shared.v4.b32 [%0], {%1,%1,%1,%1};"::"r"(dst),"r"(0):"memory");
        }
    }
    // ---- stage weights (och half) tap 0 into buf 0 ----
    for (int idx = tid; idx < Et*256; idx += NT){
        int r = idx >> 3, ch = idx & 7;
        int e = r >> 5, rl = r & 31;
        u32 dst = sbW + r*144 + ch*16;
        const char* src = (const char*)d_wm + (((size_t)(ps.l[e]*9 + 0)*64 + och*32 + rl) << 7) + ch*16;
        CP16(dst, src);
    }
    CPCOMMIT();

    // ldmatrix lane patterns
    const int g = lane >> 3, lm = lane & 7;
    const u32 patB = (u32)(((g&2)?8:0) + lm)*144 + ((g&1)?16:0);
    const u32 patA = (u32)(((g&1)?8:0) + lm)*144 + ((g&2)?16:0);
    int Arow[MT];
    #pragma unroll
    for (int j = 0; j < MT; j++)
        Arow[j] = (wm*MT + j)*16*144;

    float acc[MT][8][4];
    #pragma unroll
    for (int j = 0; j < MT; j++)
        #pragma unroll
        for (int nt = 0; nt < 8; nt++)
            #pragma unroll
            for (int q = 0; q < 4; q++) acc[j][nt][q] = 0.f;

    #pragma unroll 1
    for (int tap = 0; tap < 9; tap++){
        if (tap + 1 < 9){
            int buf = (tap + 1) % 3;
            for (int idx = tid; idx < Et*256; idx += NT){
                int r = idx >> 3, ch = idx & 7;
                int e = r >> 5, rl = r & 31;
                u32 dst = sbW + buf*WBUF + r*144 + ch*16;
                const char* src = (const char*)d_wm + (((size_t)(ps.l[e]*9 + tap + 1)*64 + och*32 + rl) << 7) + ch*16;
                CP16(dst, src);
            }
            CPCOMMIT();
            CPWAIT1();
        } else {
            CPWAIT0();
        }
        __syncthreads();   // single barrier per tap (triple-buffered weights)

        const int ky = tap / 3, kx = tap - ky*3;
        const u32 pB0 = sb + (u32)((wn2*2 + ky)*34 + kx)*144 + patB;
        const u32 pB1 = pB0 + 34*144;
        const u32 pA  = sbW + (tap % 3)*WBUF + patA;

        #pragma unroll
        for (int kk = 0; kk < 4; kk++){
            u32 b0,b1,b2,b3,b4,b5,b6,b7;
            u32 c0,c1,c2,c3,c4,c5,c6,c7;
            LDSM4(b0,b1,b2,b3, pB0 + 32*kk);
            LDSM4(b4,b5,b6,b7, pB0 + 32*kk + 16*144);
            LDSM4(c0,c1,c2,c3, pB1 + 32*kk);
            LDSM4(c4,c5,c6,c7, pB1 + 32*kk + 16*144);
            #pragma unroll
            for (int j = 0; j < MT; j++){
                u32 a0,a1,a2,a3;
                LDSM4(a0,a1,a2,a3, pA + Arow[j] + 32*kk);
                MMAH(acc[j][0], a0,a1,a2,a3, b0,b1);
                MMAH(acc[j][1], a0,a1,a2,a3, b2,b3);
                MMAH(acc[j][2], a0,a1,a2,a3, b4,b5);
                MMAH(acc[j][3], a0,a1,a2,a3, b6,b7);
                MMAH(acc[j][4], a0,a1,a2,a3, c0,c1);
                MMAH(acc[j][5], a0,a1,a2,a3, c2,c3);
                MMAH(acc[j][6], a0,a1,a2,a3, c4,c5);
                MMAH(acc[j][7], a0,a1,a2,a3, c6,c7);
            }
        }
    }

    // ---------------- epilogue ----------------
    #pragma unroll
    for (int j = 0; j < MT; j++){
        int t = wm*MT + j;
        int e = t >> 1;
        int ocb = och*32 + (t & 1)*16 + (lane >> 2);
        int mode = ps.mode[e];
        const float* add = ps.addin[e];
        #pragma unroll
        for (int nt = 0; nt < 8; nt++){
            int h = h0 + wn2*2 + (nt >> 2);
            int wcol = (nt & 3)*8 + 2*(lane & 3);
            #pragma unroll
            for (int half = 0; half < 2; half++){
                int oc = ocb + half*8;
                float v0 = acc[j][nt][half*2 + 0];
                float v1 = acc[j][nt][half*2 + 1];
                size_t base = (((size_t)b*Cc + oc)*Hc + h)*Wc + wcol;
                if (add){
                    float2 a2 = *(const float2*)(add + base);
                    v0 += a2.x; v1 += a2.y;
                }
                if (mode == 0){
                    *(float2*)((float*)ps.outA[e] + base) = make_float2(v0, v1);
                } else if (mode == 1){
                    float ai = d_ain[oc], ao = d_aout[oc];
                    v0 = ai * fmaxf(ao * v0, 0.f);
                    v1 = ai * fmaxf(ao * v1, 0.f);
                    __half* ox = (__half*)ps.outA[e];
                    size_t pos = ((size_t)b*Hc + h)*Wc + wcol;
                    ox[pos*64 + oc]     = __float2half_rn(v0);
                    ox[(pos+1)*64 + oc] = __float2half_rn(v1);
                } else {
                    float ao = d_aout[oc];
                    *(float2*)((float*)ps.outA[e] + base) = make_float2(ao*v0, ao*v1);
                }
            }
        }
    }
}

// ---------------- launch ----------------
extern "C" void kernel_launch(void* const* d_in, const int* in_sizes, int n_in,
                              void* d_out, int out_size){
    const float *x=nullptr, *a1=nullptr, *a2=nullptr, *W=nullptr;
    for (int i=0;i<n_in;i++){
        if (in_sizes[i]==TOTSZ) x=(const float*)d_in[i];
        else if (in_sizes[i]==WSZ) W=(const float*)d_in[i];
        else if (in_sizes[i]==8){ if(!a1) a1=(const float*)d_in[i]; else a2=(const float*)d_in[i]; }
    }
    float* out = (float*)d_out;

    __half *x0p,*x1p,*x2p;
    float *acc2,*acc3;
    cudaGetSymbolAddress((void**)&x0p,d_x0);
    cudaGetSymbolAddress((void**)&x1p,d_x1);
    cudaGetSymbolAddress((void**)&x2p,d_x2);
    cudaGetSymbolAddress((void**)&acc2,d_acc2);
    cudaGetSymbolAddress((void**)&acc3,d_acc3);

    // A: Et=3, band 4, NT=192 (2 RP x 3 MG, MT=2), 3 CTAs/SM -> 18 warps/SM
    // B: Et=2, band 8, NT=256 (4 RP x 2 MG, MT=2), 2 CTAs/SM -> 16 warps/SM
    // C: Et=1, band 8, NT=128 (4 RP x 1 MG, MT=2), 3 CTAs/SM -> 12 warps/SM
    const int smemA = 6*34*144  + 3*3*32*144;   // 70848  x3 = 212.5KB
    const int smemB = 10*34*144 + 3*2*32*144;   // 76608  x2
    const int smemC = 10*34*144 + 3*1*32*144;   // 62784  x3 = 188.4KB
    cudaFuncSetAttribute((conv_mma_kernel<3,4,192,3>), cudaFuncAttributeMaxDynamicSharedMemorySize, smemA);
    cudaFuncSetAttribute((conv_mma_kernel<2,8,256,2>), cudaFuncAttributeMaxDynamicSharedMemorySize, smemB);
    cudaFuncSetAttribute((conv_mma_kernel<1,8,128,3>), cudaFuncAttributeMaxDynamicSharedMemorySize, smemC);

    scales_kernel<<<1, 64>>>(a1, a2);
    wprep_kernel<<<(NEDGE*9*Cc*Cc + 255)/256, 256>>>(W);
    inprep_kernel<<<dim3(Hc, Bc), 256>>>(x);

    // Pass A: x0 -> { W0 -> x1 (mode1), W1 -> acc2 (mode0), W3 -> acc3 (mode0) }
    PassSpec pa{};
    pa.l[0]=0; pa.mode[0]=1; pa.addin[0]=nullptr; pa.outA[0]=x1p;
    pa.l[1]=1; pa.mode[1]=0; pa.addin[1]=nullptr; pa.outA[1]=acc2;
    pa.l[2]=3; pa.mode[2]=0; pa.addin[2]=nullptr; pa.outA[2]=acc3;
    pa.in = x0p;
    conv_mma_kernel<3,4,192,3><<<dim3(8, Bc, 2), 192, smemA>>>(pa);

    // Pass B: x1 -> { W2 + acc2 -> x2 (mode1), W4 + acc3 -> acc3 (mode0) }
    PassSpec pb{};
    pb.l[0]=2; pb.mode[0]=1; pb.addin[0]=acc2; pb.outA[0]=x2p;
    pb.l[1]=4; pb.mode[1]=0; pb.addin[1]=acc3; pb.outA[1]=acc3;
    pb.in = x1p;
    conv_mma_kernel<2,8,256,2><<<dim3(4, Bc, 2), 256, smemB>>>(pb);

    // Pass C: x2 -> { W5 + acc3 -> out (mode2) }
    PassSpec pc{};
    pc.l[0]=5; pc.mode[0]=2; pc.addin[0]=acc3; pc.outA[0]=out;
    pc.in = x2p;
    conv_mma_kernel<1,8,128,3><<<dim3(4, Bc, 2), 128, smemC>>>(pc);

    (void)out_size;
}

// round 16
// speedup vs baseline: 1.3456x; 1.0856x over previous
#include <cuda_runtime.h>
#include <cuda_fp16.h>
#include <cstdint>

#define Bc 128
#define Cc 64
#define Hc 32
#define Wc 32
#define NEDGE 6
#define TOTSZ (Bc*Cc*Hc*Wc)
#define WSZ   (NEDGE*Cc*Cc*9)

typedef unsigned int u32;

// ---------------- device scratch ----------------
__device__ __align__(16) __half d_x0[TOTSZ];
__device__ __align__(16) __half d_x1[TOTSZ];
__device__ __align__(16) __half d_x2[TOTSZ];
__device__ float d_acc2[TOTSZ];     // NCHW fp32
__device__ float d_acc3[TOTSZ];     // NCHW fp32
__device__ __align__(16) __half d_wm[NEDGE*9*Cc*64];   // [l][s][oc][64] fp16
__device__ float d_ain[Cc], d_aout[Cc];

// ---------------- PTX helpers (baseline sm_80+ PTX only) ----------------
__device__ __forceinline__ u32 smem_u32(const void* p){
    u32 a; asm("{ .reg .u64 t; cvta.to.shared.u64 t, %1; cvt.u32.u64 %0, t; }":"=r"(a):"l"(p)); return a;
}
#define CP16(dst,src) asm volatile("cp.async.ca.shared.global [%0], [%1], 16;"::"r"(dst),"l"(src):"memory")
#define CPCOMMIT()    asm volatile("cp.async.commit_group;":::"memory")
#define CPWAIT1()     asm volatile("cp.async.wait_group 1;":::"memory")
#define CPWAIT0()     asm volatile("cp.async.wait_group 0;":::"memory")

#define LDSM4(r0,r1,r2,r3,addr) \
    asm volatile("ldmatrix.sync.aligned.m8n8.x4.shared.b16 {%0,%1,%2,%3}, [%4];" \
        : "=r"(r0),"=r"(r1),"=r"(r2),"=r"(r3) : "r"(addr))

#define MMAH(c,a0,a1,a2,a3,b0,b1) \
    asm volatile("mma.sync.aligned.m16n8k16.row.col.f32.f16.f16.f32 " \
        "{%0,%1,%2,%3},{%4,%5,%6,%7},{%8,%9},{%0,%1,%2,%3};" \
        : "+f"((c)[0]),"+f"((c)[1]),"+f"((c)[2]),"+f"((c)[3]) \
        : "r"(a0),"r"(a1),"r"(a2),"r"(a3),"r"(b0),"r"(b1))

// ---------------- prep kernels ----------------
__global__ void scales_kernel(const float* __restrict__ a1, const float* __restrict__ a2){
    int c = threadIdx.x;
    if (c < Cc){
        float s1=0.f, s2=0.f;
        #pragma unroll
        for (int i=0;i<8;i++) if (c < 8*(i+1)) { s1+=a1[i]; s2+=a2[i]; }
        d_ain[c]=s1; d_aout[c]=s2;
    }
}

__global__ void wprep_kernel(const float* __restrict__ W){
    int idx = blockIdx.x*256 + threadIdx.x;
    if (idx >= NEDGE*9*Cc*Cc) return;
    int ci = idx & 63, t = idx >> 6;
    int oc = t & 63; t >>= 6;
    int s = t % 9, l = t / 9;
    float w = W[(((l*Cc + oc)*Cc + ci)*9) + s];
    d_wm[(size_t)((l*9 + s)*Cc + oc) * 64 + ci] = __float2half_rn(w);
}

__global__ void inprep_kernel(const float* __restrict__ x){
    __shared__ float tile[Cc][Wc+1];
    int b = blockIdx.y, h = blockIdx.x, t = threadIdx.x;
    int w = t & 31, cb = t >> 5;
    #pragma unroll
    for (int i=0;i<8;i++){
        int c = cb*8 + i;
        tile[c][w] = x[(((size_t)b*Cc + c)*Hc + h)*Wc + w];
    }
    __syncthreads();
    int w2 = t >> 3, cg = (t & 7) * 8;
    u32 hi[4];
    #pragma unroll
    for (int i=0;i<4;i++){
        int c = cg + i*2;
        float v0 = d_ain[c]   * fmaxf(tile[c][w2],   0.f);
        float v1 = d_ain[c+1] * fmaxf(tile[c+1][w2], 0.f);
        hi[i]=(u32)__half_as_ushort(__float2half_rn(v0))
             |((u32)__half_as_ushort(__float2half_rn(v1))<<16);
    }
    size_t pos = ((size_t)b*Hc + h)*Wc + w2;
    *(uint4*)(d_x0 + pos*64 + cg) = make_uint4(hi[0],hi[1],hi[2],hi[3]);
}

// ---------------- conv pass (parametric, och-split CTAs, pipelined) ----------------
struct PassSpec {
    int l[3];
    int mode[3];            // 0: fp32 NCHW acc; 1: relu -> next d_x fp16; 2: final NCHW out
    const float* addin[3];  // NCHW fp32 or null
    void* outA[3];
    const __half* in;
};

// Et edges, BAND rows/CTA, NT threads, OCC CTAs/SM; CTA owns 32 oc (blockIdx.z half).
// warps = (BAND/2 row-pairs) x MG m-groups; MT = Et*2/MG m-tiles per warp, n=8.
template<int Et, int BAND, int NT, int OCC>
__global__ __launch_bounds__(NT, OCC)
void conv_mma_kernel(PassSpec ps){
    constexpr int WARPS = NT/32;
    constexpr int RP    = BAND/2;
    constexpr int MG    = WARPS/RP;
    constexpr int MT    = (Et*2)/MG;
    constexpr int INR   = BAND + 2;
    constexpr int SM_IN = INR*34*144;
    constexpr int WBUF  = Et*32*144;
    static_assert(MG*MT == Et*2 && RP*MG == WARPS, "tiling");

    extern __shared__ __align__(16) char smem[];
    const u32 sb  = smem_u32(smem);
    const int tid = threadIdx.x;
    const int lane = tid & 31, wrp = tid >> 5;
    const int wn2 = wrp % RP, wm = wrp / RP;
    const int band = blockIdx.x, b = blockIdx.y;
    const int och = blockIdx.z;
    const int h0 = band * BAND;
    const u32 sbW = sb + SM_IN;

    // ---- stage input tile: INR*34 pos rows x 128B (+16B pad) ----
    for (int idx = tid; idx < INR*34*8; idx += NT){
        int p = idx >> 3, ch = idx & 7;
        int trow = p / 34, tcol = p - trow*34;
        int ih = h0 - 1 + trow, iw = tcol - 1;
        u32 dst = sb + p*144 + ch*16;
        if ((unsigned)ih < 32u && (unsigned)iw < 32u){
            const char* src = (const char*)(ps.in + ((size_t)((b*Hc + ih)*Wc + iw) << 6)) + ch*16;
            CP16(dst, src);
        } else {
            asm volatile("st.shared.v4.b32 [%0], {%1,%1,%1,%1};"::"r"(dst),"r"(0):"memory");
        }
    }
    // ---- stage weights (och half) tap 0 into buf 0 ----
    for (int idx = tid; idx < Et*256; idx += NT){
        int r = idx >> 3, ch = idx & 7;
        int e = r >> 5, rl = r & 31;
        u32 dst = sbW + r*144 + ch*16;
        const char* src = (const char*)d_wm + (((size_t)(ps.l[e]*9 + 0)*64 + och*32 + rl) << 7) + ch*16;
        CP16(dst, src);
    }
    CPCOMMIT();
    CPWAIT0();
    __syncthreads();   // input tile + tap0 weights visible to all; input is static hereafter

    // ldmatrix lane patterns
    const int g = lane >> 3, lm = lane & 7;
    const u32 patB = (u32)(((g&2)?8:0) + lm)*144 + ((g&1)?16:0);
    const u32 patA = (u32)(((g&1)?8:0) + lm)*144 + ((g&2)?16:0);
    int Arow[MT];
    #pragma unroll
    for (int j = 0; j < MT; j++)
        Arow[j] = (wm*MT + j)*16*144;

    float acc[MT][8][4];
    #pragma unroll
    for (int j = 0; j < MT; j++)
        #pragma unroll
        for (int nt = 0; nt < 8; nt++)
            #pragma unroll
            for (int q = 0; q < 4; q++) acc[j][nt][q] = 0.f;

    #pragma unroll 1
    for (int tap = 0; tap < 9; tap++){
        const int ky = tap / 3, kx = tap - ky*3;
        const u32 pB0 = sb + (u32)((wn2*2 + ky)*34 + kx)*144 + patB;
        const u32 pB1 = pB0 + 34*144;

        // double-buffered B fragments; kk=0 issued BEFORE the barrier (input is static)
        u32 bf[2][16];
        LDSM4(bf[0][0], bf[0][1], bf[0][2], bf[0][3],  pB0);
        LDSM4(bf[0][4], bf[0][5], bf[0][6], bf[0][7],  pB0 + 16*144);
        LDSM4(bf[0][8], bf[0][9], bf[0][10],bf[0][11], pB1);
        LDSM4(bf[0][12],bf[0][13],bf[0][14],bf[0][15], pB1 + 16*144);

        // stage next tap's weights, then wait for THIS tap's weights
        if (tap + 1 < 9){
            int buf = (tap + 1) % 3;
            for (int idx = tid; idx < Et*256; idx += NT){
                int r = idx >> 3, ch = idx & 7;
                int e = r >> 5, rl = r & 31;
                u32 dst = sbW + buf*WBUF + r*144 + ch*16;
                const char* src = (const char*)d_wm + (((size_t)(ps.l[e]*9 + tap + 1)*64 + och*32 + rl) << 7) + ch*16;
                CP16(dst, src);
            }
            CPCOMMIT();
            CPWAIT1();
        } else {
            CPWAIT0();
        }
        __syncthreads();   // single barrier per tap (triple-buffered weights)

        const u32 pA = sbW + (tap % 3)*WBUF + patA;

        #pragma unroll
        for (int kk = 0; kk < 4; kk++){
            const u32* bc = bf[kk & 1];
            // prefetch next kk's B fragments while this kk's MMAs run
            if (kk < 3){
                u32* bn = bf[(kk + 1) & 1];
                LDSM4(bn[0], bn[1], bn[2], bn[3],  pB0 + 32*(kk+1));
                LDSM4(bn[4], bn[5], bn[6], bn[7],  pB0 + 32*(kk+1) + 16*144);
                LDSM4(bn[8], bn[9], bn[10],bn[11], pB1 + 32*(kk+1));
                LDSM4(bn[12],bn[13],bn[14],bn[15], pB1 + 32*(kk+1) + 16*144);
            }
            #pragma unroll
            for (int j = 0; j < MT; j++){
                u32 a0,a1,a2,a3;
                LDSM4(a0,a1,a2,a3, pA + Arow[j] + 32*kk);
                MMAH(acc[j][0], a0,a1,a2,a3, bc[0], bc[1]);
                MMAH(acc[j][1], a0,a1,a2,a3, bc[2], bc[3]);
                MMAH(acc[j][2], a0,a1,a2,a3, bc[4], bc[5]);
                MMAH(acc[j][3], a0,a1,a2,a3, bc[6], bc[7]);
                MMAH(acc[j][4], a0,a1,a2,a3, bc[8], bc[9]);
                MMAH(acc[j][5], a0,a1,a2,a3, bc[10],bc[11]);
                MMAH(acc[j][6], a0,a1,a2,a3, bc[12],bc[13]);
                MMAH(acc[j][7], a0,a1,a2,a3, bc[14],bc[15]);
            }
        }
    }

    // ---------------- epilogue ----------------
    #pragma unroll
    for (int j = 0; j < MT; j++){
        int t = wm*MT + j;
        int e = t >> 1;
        int ocb = och*32 + (t & 1)*16 + (lane >> 2);
        int mode = ps.mode[e];
        const float* add = ps.addin[e];
        #pragma unroll
        for (int nt = 0; nt < 8; nt++){
            int h = h0 + wn2*2 + (nt >> 2);
            int wcol = (nt & 3)*8 + 2*(lane & 3);
            #pragma unroll
            for (int half = 0; half < 2; half++){
                int oc = ocb + half*8;
                float v0 = acc[j][nt][half*2 + 0];
                float v1 = acc[j][nt][half*2 + 1];
                size_t base = (((size_t)b*Cc + oc)*Hc + h)*Wc + wcol;
                if (add){
                    float2 a2 = *(const float2*)(add + base);
                    v0 += a2.x; v1 += a2.y;
                }
                if (mode == 0){
                    *(float2*)((float*)ps.outA[e] + base) = make_float2(v0, v1);
                } else if (mode == 1){
                    float ai = d_ain[oc], ao = d_aout[oc];
                    v0 = ai * fmaxf(ao * v0, 0.f);
                    v1 = ai * fmaxf(ao * v1, 0.f);
                    __half* ox = (__half*)ps.outA[e];
                    size_t pos = ((size_t)b*Hc + h)*Wc + wcol;
                    ox[pos*64 + oc]     = __float2half_rn(v0);
                    ox[(pos+1)*64 + oc] = __float2half_rn(v1);
                } else {
                    float ao = d_aout[oc];
                    *(float2*)((float*)ps.outA[e] + base) = make_float2(ao*v0, ao*v1);
                }
            }
        }
    }
}

// ---------------- launch ----------------
extern "C" void kernel_launch(void* const* d_in, const int* in_sizes, int n_in,
                              void* d_out, int out_size){
    const float *x=nullptr, *a1=nullptr, *a2=nullptr, *W=nullptr;
    for (int i=0;i<n_in;i++){
        if (in_sizes[i]==TOTSZ) x=(const float*)d_in[i];
        else if (in_sizes[i]==WSZ) W=(const float*)d_in[i];
        else if (in_sizes[i]==8){ if(!a1) a1=(const float*)d_in[i]; else a2=(const float*)d_in[i]; }
    }
    float* out = (float*)d_out;

    __half *x0p,*x1p,*x2p;
    float *acc2,*acc3;
    cudaGetSymbolAddress((void**)&x0p,d_x0);
    cudaGetSymbolAddress((void**)&x1p,d_x1);
    cudaGetSymbolAddress((void**)&x2p,d_x2);
    cudaGetSymbolAddress((void**)&acc2,d_acc2);
    cudaGetSymbolAddress((void**)&acc3,d_acc3);

    // R13 shapes (best known), pipelined:
    // A: Et=3, band 4, NT=128 (MT=3), 3 CTAs/SM
    // B: Et=2, band 8, NT=256 (MT=2), 2 CTAs/SM
    // C: Et=1, band 8, NT=256 (MT=1), 2 CTAs/SM
    const int smemA = 6*34*144  + 3*3*32*144;   // 70848
    const int smemB = 10*34*144 + 3*2*32*144;   // 76608
    const int smemC = 10*34*144 + 3*1*32*144;   // 62784
    cudaFuncSetAttribute((conv_mma_kernel<3,4,128,3>), cudaFuncAttributeMaxDynamicSharedMemorySize, smemA);
    cudaFuncSetAttribute((conv_mma_kernel<2,8,256,2>), cudaFuncAttributeMaxDynamicSharedMemorySize, smemB);
    cudaFuncSetAttribute((conv_mma_kernel<1,8,256,2>), cudaFuncAttributeMaxDynamicSharedMemorySize, smemC);

    scales_kernel<<<1, 64>>>(a1, a2);
    wprep_kernel<<<(NEDGE*9*Cc*Cc + 255)/256, 256>>>(W);
    inprep_kernel<<<dim3(Hc, Bc), 256>>>(x);

    // Pass A: x0 -> { W0 -> x1 (mode1), W1 -> acc2 (mode0), W3 -> acc3 (mode0) }
    PassSpec pa{};
    pa.l[0]=0; pa.mode[0]=1; pa.addin[0]=nullptr; pa.outA[0]=x1p;
    pa.l[1]=1; pa.mode[1]=0; pa.addin[1]=nullptr; pa.outA[1]=acc2;
    pa.l[2]=3; pa.mode[2]=0; pa.addin[2]=nullptr; pa.outA[2]=acc3;
    pa.in = x0p;
    conv_mma_kernel<3,4,128,3><<<dim3(8, Bc, 2), 128, smemA>>>(pa);

    // Pass B: x1 -> { W2 + acc2 -> x2 (mode1), W4 + acc3 -> acc3 (mode0) }
    PassSpec pb{};
    pb.l[0]=2; pb.mode[0]=1; pb.addin[0]=acc2; pb.outA[0]=x2p;
    pb.l[1]=4; pb.mode[1]=0; pb.addin[1]=acc3; pb.outA[1]=acc3;
    pb.in = x1p;
    conv_mma_kernel<2,8,256,2><<<dim3(4, Bc, 2), 256, smemB>>>(pb);

    // Pass C: x2 -> { W5 + acc3 -> out (mode2) }
    PassSpec pc{};
    pc.l[0]=5; pc.mode[0]=2; pc.addin[0]=acc3; pc.outA[0]=out;
    pc.in = x2p;
    conv_mma_kernel<1,8,256,2><<<dim3(4, Bc, 2), 256, smemC>>>(pc);

    (void)out_size;
}